// round 15
// baseline (speedup 1.0000x reference)
#include <cuda_runtime.h>

#define BB 2
#define NN 2048
#define DIN 1024
#define DOUT 1024
#define HH 16
#define HD 64

// Scratch (static device allocations — allowed)
__device__ float g_q[BB*HH*NN*HD];
__device__ float g_k[BB*HH*NN*HD];
__device__ float g_v[BB*HH*NN*HD];
__device__ float g_ctx[BB*NN*DOUT];

__device__ __forceinline__ unsigned f2tf32(float f) {
    unsigned r;
    asm("cvt.rna.tf32.f32 %0, %1;" : "=r"(r) : "f"(f));
    return r;
}

__device__ __forceinline__ void mma_tf32(float c[4],
    unsigned a0, unsigned a1, unsigned a2, unsigned a3,
    unsigned b0, unsigned b1)
{
    asm volatile(
        "mma.sync.aligned.m16n8k8.row.col.f32.tf32.tf32.f32 "
        "{%0,%1,%2,%3}, {%4,%5,%6,%7}, {%8,%9}, {%0,%1,%2,%3};"
        : "+f"(c[0]), "+f"(c[1]), "+f"(c[2]), "+f"(c[3])
        : "r"(a0), "r"(a1), "r"(a2), "r"(a3), "r"(b0), "r"(b1));
}

// ---------------------------------------------------------------------------
// GEMM core with VECTORIZED fragment loads (shared by qkv and out):
//   A stored permuted:  As[row][p], p = (k&3)*8 + (k>>2)
//     -> a thread's 8 k-values per row (k ≡ tg mod 4) are contiguous:
//        uint4 at As[row][tg*8 + half*4] covers kk = 16*half + {0,8} frags.
//   B stored col-swizzled: Bs[k][col'], col' = (col&7)*16 + ((col>>3)&3)
//                                              + ((col>>5)<<2)
//     -> the 4 nt-columns (wn + nt*8 + g) are one uint4 at
//        Bs[k][16g + 4*(wn>>5)], component nt.
// Inner loop per 32-k tile: 16+8 LDS.128 + 64 HMMA (was ~160 scalar LDS).
// Pre-converted tf32 -> bit-identical results to R12/R13.
// ---------------------------------------------------------------------------
#define GEMM_TC_BODY(A_SRC_ROW_EXPR, B_SRC_ROW_EXPR)                          \
    __shared__ unsigned As[128][36];                                          \
    __shared__ unsigned Bs[32][132];                                          \
    const int tid  = threadIdx.x;                                             \
    const int warp = tid >> 5;                                                \
    const int lane = tid & 31;                                                \
    const int g    = lane >> 2;                                               \
    const int tg   = lane & 3;                                                \
    const int wm   = (warp >> 2) * 64;                                        \
    const int wn   = (warp & 3) * 32;                                         \
    const int wq4  = (wn >> 5) << 2;                                          \
    const int bm   = blockIdx.y * 128;                                        \
    const int bn   = blockIdx.x * 128;                                        \
    float c[16][4];                                                           \
    _Pragma("unroll")                                                         \
    for (int t = 0; t < 16; t++)                                              \
        _Pragma("unroll")                                                     \
        for (int i = 0; i < 4; i++) c[t][i] = 0.f;                            \
    for (int k0 = 0; k0 < 1024; k0 += 32) {                                   \
        _Pragma("unroll")                                                     \
        for (int s = 0; s < 4; s++) {                                         \
            int slot = tid + s * 256;                                         \
            int r  = slot >> 3;                                               \
            int tt = slot & 7;                                                \
            int c4 = tt << 2;                                                 \
            float4 v = *(const float4*)&(A_SRC_ROW_EXPR);                     \
            As[r][     tt] = f2tf32(v.x);                                     \
            As[r][ 8 + tt] = f2tf32(v.y);                                     \
            As[r][16 + tt] = f2tf32(v.z);                                     \
            As[r][24 + tt] = f2tf32(v.w);                                     \
            (void)c4;                                                         \
        }                                                                     \
        _Pragma("unroll")                                                     \
        for (int s = 0; s < 4; s++) {                                         \
            int slot = tid + s * 256;                                         \
            int kr = slot >> 5;                                               \
            int c4 = (slot & 31) << 2;                                        \
            float4 v = *(const float4*)&(B_SRC_ROW_EXPR);                     \
            int cb = ((c4 & 7) << 4) + ((c4 >> 3) & 3) + ((c4 >> 5) << 2);    \
            Bs[kr][cb     ] = f2tf32(v.x);                                    \
            Bs[kr][cb + 16] = f2tf32(v.y);                                    \
            Bs[kr][cb + 32] = f2tf32(v.z);                                    \
            Bs[kr][cb + 48] = f2tf32(v.w);                                    \
        }                                                                     \
        __syncthreads();                                                      \
        _Pragma("unroll")                                                     \
        for (int half = 0; half < 2; half++) {                                \
            uint4 aw[4][2];                                                   \
            _Pragma("unroll")                                                 \
            for (int mt = 0; mt < 4; mt++) {                                  \
                int row = wm + mt * 16 + g;                                   \
                aw[mt][0] = *(const uint4*)&As[row    ][tg * 8 + half * 4];   \
                aw[mt][1] = *(const uint4*)&As[row + 8][tg * 8 + half * 4];   \
            }                                                                 \
            _Pragma("unroll")                                                 \
            for (int kkl = 0; kkl < 2; kkl++) {                               \
                int kk = half * 16 + kkl * 8;                                 \
                uint4 bw0 = *(const uint4*)&Bs[kk + tg    ][g * 16 + wq4];    \
                uint4 bw1 = *(const uint4*)&Bs[kk + tg + 4][g * 16 + wq4];    \
                const unsigned* b0 = (const unsigned*)&bw0;                   \
                const unsigned* b1 = (const unsigned*)&bw1;                   \
                _Pragma("unroll")                                             \
                for (int mt = 0; mt < 4; mt++) {                              \
                    const unsigned* a0p = (const unsigned*)&aw[mt][0];        \
                    const unsigned* a1p = (const unsigned*)&aw[mt][1];        \
                    unsigned a0 = a0p[kkl * 2    ];                           \
                    unsigned a1 = a1p[kkl * 2    ];                           \
                    unsigned a2 = a0p[kkl * 2 + 1];                           \
                    unsigned a3 = a1p[kkl * 2 + 1];                           \
                    _Pragma("unroll")                                         \
                    for (int nt = 0; nt < 4; nt++)                            \
                        mma_tf32(c[mt * 4 + nt], a0, a1, a2, a3,              \
                                 b0[nt], b1[nt]);                             \
                }                                                             \
            }                                                                 \
        }                                                                     \
        __syncthreads();                                                      \
    }

// ---------------------------------------------------------------------------
// Fused QKV GEMM.
// ---------------------------------------------------------------------------
__global__ __launch_bounds__(256, 2) void qkv_gemm_tc(
    const float* __restrict__ x,
    const float* __restrict__ Wq,
    const float* __restrict__ Wk,
    const float* __restrict__ Wv)
{
    const float* W = (blockIdx.z == 0) ? Wq : (blockIdx.z == 1 ? Wk : Wv);
    float* out = (blockIdx.z == 0) ? g_q : (blockIdx.z == 1 ? g_k : g_v);

    GEMM_TC_BODY(x[(size_t)(bm + r) * DIN + k0 + c4],
                 W[(size_t)(k0 + kr) * DOUT + bn + c4])

    // Epilogue: scatter to [b, h, n, d]
    #pragma unroll
    for (int mt = 0; mt < 4; mt++) {
        #pragma unroll
        for (int nt = 0; nt < 4; nt++) {
            int col = bn + wn + nt * 8 + tg * 2;
            int h_ = col >> 6;
            int d_ = col & 63;
            #pragma unroll
            for (int half = 0; half < 2; half++) {
                int row = bm + wm + mt * 16 + g + half * 8;
                int b_ = row >> 11;
                int n_ = row & 2047;
                float* p = &out[(((size_t)(b_ * HH + h_) * NN) + n_) * HD + d_];
                p[0] = c[mt * 4 + nt][half * 2 + 0];
                p[1] = c[mt * 4 + nt][half * 2 + 1];
            }
        }
    }
}

// ---------------------------------------------------------------------------
// Output GEMM: d_out = g_ctx @ Wo + bo.
// ---------------------------------------------------------------------------
__global__ __launch_bounds__(256, 2) void out_gemm_tc(
    const float* __restrict__ Wo,
    const float* __restrict__ bo,
    float* __restrict__ out)
{
    GEMM_TC_BODY(g_ctx[(size_t)(bm + r) * DOUT + k0 + c4],
                 Wo[(size_t)(k0 + kr) * DOUT + bn + c4])

    #pragma unroll
    for (int mt = 0; mt < 4; mt++) {
        #pragma unroll
        for (int nt = 0; nt < 4; nt++) {
            int col = bn + wn + nt * 8 + tg * 2;
            float b0 = bo[col], b1 = bo[col + 1];
            #pragma unroll
            for (int half = 0; half < 2; half++) {
                int row = bm + wm + mt * 16 + g + half * 8;
                float* p = &out[(size_t)row * DOUT + col];
                p[0] = c[mt * 4 + nt][half * 2 + 0] + b0;
                p[1] = c[mt * 4 + nt][half * 2 + 1] + b1;
            }
        }
    }
}

// ---------------------------------------------------------------------------
// Tensor-core flash attention. UNCHANGED from R12/R13 (passing, ~258us):
// Q/K/V/P single-rounded tf32 in SMEM, 113KB, 2 blocks/SM, largest-first.
// NOTE: the Ks fragment read MUST stay transposed (Ks[col*68 + kk+tg]) —
// for S = Q K^T the MMA reduction dim is d, keys are the n dim.
// ---------------------------------------------------------------------------
#define QS_OFF 0
#define KS_OFF (128*68)
#define VS_OFF (KS_OFF + 64*68)
#define PS_OFF (VS_OFF + 64*68)
#define RS_OFF (PS_OFF + 128*68)
#define LS_OFF (RS_OFF + 2048)
#define ATTN_SMEM_FLOATS (LS_OFF + 128)
#define ATTN_SMEM_BYTES (ATTN_SMEM_FLOATS * 4)

__global__ __launch_bounds__(256) void attn_tc(
    const float* __restrict__ wp,
    const float* __restrict__ vp)
{
    extern __shared__ float sm[];
    unsigned* Qs = (unsigned*)sm + QS_OFF;
    unsigned* Ks = (unsigned*)sm + KS_OFF;
    unsigned* Vs = (unsigned*)sm + VS_OFF;
    unsigned* Ps = (unsigned*)sm + PS_OFF;
    float*    Rs = sm + RS_OFF;
    float*    Ls = sm + LS_OFF;

    const int qb  = (NN / 128 - 1) - blockIdx.x;   // largest-first
    const int h   = blockIdx.y;
    const int b   = blockIdx.z;
    const int tid = threadIdx.x;
    const int warp = tid >> 5;
    const int lane = tid & 31;
    const int g  = lane >> 2;
    const int tg = lane & 3;
    const int wm = (warp >> 1) * 32;
    const int wn = (warp & 1) * 32;

    const size_t head_off = (size_t)(b * HH + h) * NN * HD;
    const float* qbase = g_q + head_off;
    const float* kbase = g_k + head_off;
    const float* vbase = g_v + head_off;

    const float wh = wp[h];
    const float vh = vp[h];
    const float c1 = 1.f + __expf(vh);

    for (int i = tid; i < NN; i += 256)
        Rs[i] = c1 / (1.f + __expf(vh - wh * (float)i)) * 0.125f;
    if (tid < 128) Ls[tid] = 0.f;

    #pragma unroll
    for (int s = 0; s < 8; s++) {
        int slot = tid + s * 256;
        int r  = slot >> 4;
        int c4 = (slot & 15) << 2;
        float4 v = *(const float4*)&qbase[(size_t)(qb * 128 + r) * HD + c4];
        uint4 u = { f2tf32(v.x), f2tf32(v.y), f2tf32(v.z), f2tf32(v.w) };
        *(uint4*)&Qs[r * 68 + c4] = u;
    }
    __syncthreads();

    float co[2][4][4];
    #pragma unroll
    for (int mt = 0; mt < 2; mt++)
        #pragma unroll
        for (int nt = 0; nt < 4; nt++)
            #pragma unroll
            for (int i = 0; i < 4; i++) co[mt][nt][i] = 0.f;

    const int ktmax = (qb + 1) * 2;
    for (int kt = 0; kt < ktmax; kt++) {
        const int k0 = kt * 64;

        #pragma unroll
        for (int s = 0; s < 4; s++) {
            int slot = tid + s * 256;
            int r  = slot >> 4;
            int c4 = (slot & 15) << 2;
            float4 kv = *(const float4*)&kbase[(size_t)(k0 + r) * HD + c4];
            float4 vv = *(const float4*)&vbase[(size_t)(k0 + r) * HD + c4];
            uint4 ku = { f2tf32(kv.x), f2tf32(kv.y), f2tf32(kv.z), f2tf32(kv.w) };
            uint4 vu = { f2tf32(vv.x), f2tf32(vv.y), f2tf32(vv.z), f2tf32(vv.w) };
            *(uint4*)&Ks[r * 68 + c4] = ku;
            *(uint4*)&Vs[r * 68 + c4] = vu;
        }
        __syncthreads();

        float cs[2][4][4];
        #pragma unroll
        for (int mt = 0; mt < 2; mt++)
            #pragma unroll
            for (int nt = 0; nt < 4; nt++)
                #pragma unroll
                for (int i = 0; i < 4; i++) cs[mt][nt][i] = 0.f;

        #pragma unroll
        for (int kk = 0; kk < 64; kk += 8) {
            unsigned a[2][4], bb[4][2];
            #pragma unroll
            for (int mt = 0; mt < 2; mt++) {
                int row = wm + mt * 16 + g;
                a[mt][0] = Qs[row * 68 + kk + tg];
                a[mt][1] = Qs[(row + 8) * 68 + kk + tg];
                a[mt][2] = Qs[row * 68 + kk + tg + 4];
                a[mt][3] = Qs[(row + 8) * 68 + kk + tg + 4];
            }
            #pragma unroll
            for (int nt = 0; nt < 4; nt++) {
                int col = wn + nt * 8 + g;   // key index within tile
                bb[nt][0] = Ks[col * 68 + kk + tg    ];
                bb[nt][1] = Ks[col * 68 + kk + tg + 4];
            }
            #pragma unroll
            for (int mt = 0; mt < 2; mt++)
                #pragma unroll
                for (int nt = 0; nt < 4; nt++)
                    mma_tf32(cs[mt][nt],
                             a[mt][0], a[mt][1], a[mt][2], a[mt][3],
                             bb[nt][0], bb[nt][1]);
        }

        float rp[2][2] = {{0.f, 0.f}, {0.f, 0.f}};
        #pragma unroll
        for (int mt = 0; mt < 2; mt++) {
            #pragma unroll
            for (int nt = 0; nt < 4; nt++) {
                #pragma unroll
                for (int i = 0; i < 4; i++) {
                    int half = i >> 1;
                    int row_l = wm + mt * 16 + g + half * 8;
                    int col = wn + nt * 8 + tg * 2 + (i & 1);
                    int R = (qb * 128 + row_l) - (k0 + col);
                    float s = fmaxf(cs[mt][nt][i], 0.f);
                    float p = (R >= 0) ? __expf(s * Rs[R]) : 0.f;
                    unsigned pt = f2tf32(p);
                    Ps[row_l * 68 + col] = pt;
                    rp[mt][half] += __uint_as_float(pt);
                }
            }
        }
        #pragma unroll
        for (int mt = 0; mt < 2; mt++)
            #pragma unroll
            for (int half = 0; half < 2; half++) {
                float v = rp[mt][half];
                v += __shfl_xor_sync(0xffffffff, v, 1);
                v += __shfl_xor_sync(0xffffffff, v, 2);
                if (tg == 0)
                    atomicAdd(&Ls[wm + mt * 16 + g + half * 8], v);
            }
        __syncthreads();

        #pragma unroll
        for (int kk = 0; kk < 64; kk += 8) {
            unsigned pa[2][4], bb[4][2];
            #pragma unroll
            for (int mt = 0; mt < 2; mt++) {
                int row = wm + mt * 16 + g;
                pa[mt][0] = Ps[row * 68 + kk + tg];
                pa[mt][1] = Ps[(row + 8) * 68 + kk + tg];
                pa[mt][2] = Ps[row * 68 + kk + tg + 4];
                pa[mt][3] = Ps[(row + 8) * 68 + kk + tg + 4];
            }
            #pragma unroll
            for (int nt = 0; nt < 4; nt++) {
                int col = wn + nt * 8 + g;   // d index
                bb[nt][0] = Vs[(kk + tg) * 68 + col];
                bb[nt][1] = Vs[(kk + tg + 4) * 68 + col];
            }
            #pragma unroll
            for (int mt = 0; mt < 2; mt++)
                #pragma unroll
                for (int nt = 0; nt < 4; nt++)
                    mma_tf32(co[mt][nt],
                             pa[mt][0], pa[mt][1], pa[mt][2], pa[mt][3],
                             bb[nt][0], bb[nt][1]);
        }
        __syncthreads();
    }

    #pragma unroll
    for (int mt = 0; mt < 2; mt++) {
        #pragma unroll
        for (int half = 0; half < 2; half++) {
            int row_l = wm + mt * 16 + g + half * 8;
            float inv = 1.f / Ls[row_l];
            int n_ = qb * 128 + row_l;
            float* op = g_ctx + ((size_t)(b * NN + n_) * DOUT) + h * HD;
            #pragma unroll
            for (int nt = 0; nt < 4; nt++) {
                int col = wn + nt * 8 + tg * 2;
                op[col]     = co[mt][nt][half * 2 + 0] * inv;
                op[col + 1] = co[mt][nt][half * 2 + 1] * inv;
            }
        }
    }
}

// ---------------------------------------------------------------------------
extern "C" void kernel_launch(void* const* d_in, const int* in_sizes, int n_in,
                              void* d_out, int out_size)
{
    const float* x  = (const float*)d_in[0];
    const float* Wq = (const float*)d_in[1];
    const float* Wk = (const float*)d_in[2];
    const float* Wv = (const float*)d_in[3];
    const float* Wo = (const float*)d_in[4];
    const float* bo = (const float*)d_in[5];
    const float* w  = (const float*)d_in[6];
    const float* v  = (const float*)d_in[7];
    float* out = (float*)d_out;

    cudaFuncSetAttribute(attn_tc,
        cudaFuncAttributeMaxDynamicSharedMemorySize, ATTN_SMEM_BYTES);

    dim3 g1(DOUT / 128, (BB * NN) / 128, 3);
    qkv_gemm_tc<<<g1, 256>>>(x, Wq, Wk, Wv);

    dim3 g2(NN / 128, HH, BB);
    attn_tc<<<g2, 256, ATTN_SMEM_BYTES>>>(w, v);

    dim3 g3(DOUT / 128, (BB * NN) / 128, 1);
    out_gemm_tc<<<g3, 256>>>(Wo, bo, out);
}